// round 1
// baseline (speedup 1.0000x reference)
#include <cuda_runtime.h>

// Problem shape (fixed): pre_spikes [8,1,8192] f32, W [8192,8192] f32,
// thr [8,1,8192] f32, const_inp [8,1,8192] f32 -> out [8,1,8192] f32.
#define BB     8
#define MM     8192
#define NN     8192
#define KSPLIT 32
#define K_TILE (MM / KSPLIT)      // 256
#define TPB    128
#define VEC    4
#define NCOLS  (TPB * VEC)        // 512 columns per block
#define NTILES (NN / NCOLS)       // 16
#define SPIKE_CAP 0.9f

// Deterministic partial-sum scratch: [KSPLIT][B][N] = 8 MB.
__device__ float g_scratch[(size_t)KSPLIT * BB * NN];

#define FMA4(a, s, w)                         \
    do {                                      \
        (a).x = fmaf((s), (w).x, (a).x);      \
        (a).y = fmaf((s), (w).y, (a).y);      \
        (a).z = fmaf((s), (w).z, (a).z);      \
        (a).w = fmaf((s), (w).w, (a).w);      \
    } while (0)

__global__ __launch_bounds__(TPB)
void snn_gemv_partial(const float* __restrict__ pre,
                      const float* __restrict__ W)
{
    // Shared pre-spike chunk laid out [m][b] so 2x LDS.128 (broadcast) per row
    // fetch all 8 batch amplitudes.
    __shared__ float sp[K_TILE][BB];

    const int ks = blockIdx.y;
    const int k0 = ks * K_TILE;
    const int n0 = blockIdx.x * NCOLS + threadIdx.x * VEC;

    // Stage pre[b][k0 : k0+K_TILE] into shared (coalesced along m per batch).
    for (int i = threadIdx.x; i < K_TILE * BB; i += TPB) {
        const int b = i / K_TILE;
        const int m = i - b * K_TILE;
        sp[m][b] = pre[(size_t)b * MM + k0 + m];
    }
    __syncthreads();

    float4 acc0 = make_float4(0.f, 0.f, 0.f, 0.f);
    float4 acc1 = acc0, acc2 = acc0, acc3 = acc0;
    float4 acc4 = acc0, acc5 = acc0, acc6 = acc0, acc7 = acc0;

    const float4* __restrict__ wp =
        reinterpret_cast<const float4*>(W + (size_t)k0 * NN + n0);
    const size_t wstride = NN / VEC;   // float4 row stride

#pragma unroll 8
    for (int m = 0; m < K_TILE; m++) {
        const float4 w = wp[(size_t)m * wstride];     // coalesced 16B, W read once
        const float4* pv = reinterpret_cast<const float4*>(&sp[m][0]);
        const float4 p0 = pv[0];                      // batches 0..3 (broadcast LDS)
        const float4 p1 = pv[1];                      // batches 4..7
        FMA4(acc0, p0.x, w);
        FMA4(acc1, p0.y, w);
        FMA4(acc2, p0.z, w);
        FMA4(acc3, p0.w, w);
        FMA4(acc4, p1.x, w);
        FMA4(acc5, p1.y, w);
        FMA4(acc6, p1.z, w);
        FMA4(acc7, p1.w, w);
    }

    // Each (ks, b, n) slot written exactly once -> no init, no atomics.
    float* base = &g_scratch[(size_t)ks * BB * NN];
    *reinterpret_cast<float4*>(base + (size_t)0 * NN + n0) = acc0;
    *reinterpret_cast<float4*>(base + (size_t)1 * NN + n0) = acc1;
    *reinterpret_cast<float4*>(base + (size_t)2 * NN + n0) = acc2;
    *reinterpret_cast<float4*>(base + (size_t)3 * NN + n0) = acc3;
    *reinterpret_cast<float4*>(base + (size_t)4 * NN + n0) = acc4;
    *reinterpret_cast<float4*>(base + (size_t)5 * NN + n0) = acc5;
    *reinterpret_cast<float4*>(base + (size_t)6 * NN + n0) = acc6;
    *reinterpret_cast<float4*>(base + (size_t)7 * NN + n0) = acc7;
}

__global__ __launch_bounds__(256)
void snn_epilogue(const float* __restrict__ thr,
                  const float* __restrict__ cinp,
                  float* __restrict__ out)
{
    const int i = (blockIdx.x * 256 + threadIdx.x) * VEC;  // over B*N elements
    float4 s = *reinterpret_cast<const float4*>(cinp + i);
#pragma unroll
    for (int ks = 0; ks < KSPLIT; ks++) {
        const float4 v = *reinterpret_cast<const float4*>(
            &g_scratch[(size_t)ks * BB * NN + i]);
        s.x += v.x; s.y += v.y; s.z += v.z; s.w += v.w;
    }
    const float4 t = *reinterpret_cast<const float4*>(thr + i);
    s.x = fminf(fmaxf(s.x - t.x, 0.f), SPIKE_CAP);
    s.y = fminf(fmaxf(s.y - t.y, 0.f), SPIKE_CAP);
    s.z = fminf(fmaxf(s.z - t.z, 0.f), SPIKE_CAP);
    s.w = fminf(fmaxf(s.w - t.w, 0.f), SPIKE_CAP);
    *reinterpret_cast<float4*>(out + i) = s;
}

extern "C" void kernel_launch(void* const* d_in, const int* in_sizes, int n_in,
                              void* d_out, int out_size)
{
    const float* pre  = (const float*)d_in[0];  // pre_spikes [8,1,8192]
    const float* W    = (const float*)d_in[1];  // W [8192,8192]
    const float* thr  = (const float*)d_in[2];  // thr [8,1,8192]
    const float* cinp = (const float*)d_in[3];  // const_inp [8,1,8192]
    float* out = (float*)d_out;

    dim3 grid(NTILES, KSPLIT);
    snn_gemv_partial<<<grid, TPB>>>(pre, W);

    const int n_elems = BB * NN;                       // 65536
    snn_epilogue<<<n_elems / (VEC * 256), 256>>>(thr, cinp, out);
}